// round 3
// baseline (speedup 1.0000x reference)
#include <cuda_runtime.h>
#include <math.h>
#include <stdint.h>

#define GB       8
#define GH       32
#define GW       64
#define FULL_H   128
#define FULL_W   512
#define NFFT     1024
#define HOP      256
#define NK       513
#define NFRAMES  512
#define LSIG     130816
#define NSAMP    131072
#define NTOT     (GB*NFRAMES*NK)
#define OUT_AUDIO (GB*NSAMP)
#define OUT_FS    (GB*FULL_H*FULL_W)

#define TWOPI_F  6.28318548202514648438f   /* f32(2*pi), 0x40C90FDB */

// ---------------------------------------------------------------------------
// Device scratch
// ---------------------------------------------------------------------------
__device__ float   g_win[NFFT];      // f32 hann, mimicking JAX rounding
__device__ float   g_win2[NFFT];     // fl(win*win)
__device__ double2 g_twd[NFFT/2];    // exact f64 twiddles e^{-2pi i k/N}
__device__ float   g_mag[NTOT];
__device__ float2  g_S[NTOT];
__device__ float2  g_T[NTOT];
__device__ float   g_frames[GB*NFRAMES*NFFT];
__device__ float   g_audio[GB*LSIG];
__device__ float   g_maxv[GB];

// ---------------------------------------------------------------------------
// Tables. Window arg computed in f32 exactly like JAX (2pi_f32 * n / 1024 in
// f32), then exact trig in f64, rounded once.
// ---------------------------------------------------------------------------
__global__ void k_init_tables() {
    int i = blockIdx.x * blockDim.x + threadIdx.x;
    if (i < NFFT) {
        float af = __fdiv_rn(__fmul_rn(TWOPI_F, (float)i), 1024.0f);
        float c  = (float)cos((double)af);
        float w  = __fmul_rn(0.5f, __fsub_rn(1.0f, c));
        g_win[i]  = w;
        g_win2[i] = __fmul_rn(w, w);
    }
    if (i < NFFT/2) {
        double a = 2.0 * M_PI * (double)i / (double)NFFT;
        g_twd[i] = make_double2(cos(a), -sin(a));
    }
}

// ---------------------------------------------------------------------------
// threefry2x32, key (0,1)
// ---------------------------------------------------------------------------
__device__ __forceinline__ unsigned rotl32(unsigned x, int r) {
    return (x << r) | (x >> (32 - r));
}
__device__ __forceinline__ uint2 threefry_01(unsigned c0, unsigned c1) {
    const unsigned k0 = 0u, k1 = 1u;
    const unsigned k2 = 0x1BD11BDAu ^ k0 ^ k1;
    unsigned x0 = c0 + k0, x1 = c1 + k1;
#define TFR(r) { x0 += x1; x1 = rotl32(x1, (r)); x1 ^= x0; }
    TFR(13) TFR(15) TFR(26) TFR(6)
    x0 += k1; x1 += k2 + 1u;
    TFR(17) TFR(29) TFR(16) TFR(24)
    x0 += k2; x1 += k0 + 2u;
    TFR(13) TFR(15) TFR(26) TFR(6)
    x0 += k0; x1 += k1 + 3u;
    TFR(17) TFR(29) TFR(16) TFR(24)
    x0 += k1; x1 += k2 + 4u;
    TFR(13) TFR(15) TFR(26) TFR(6)
    x0 += k2; x1 += k0 + 5u;
#undef TFR
    return make_uint2(x0, x1);
}

// ---------------------------------------------------------------------------
// 1024-pt radix-2 complex FFT, all-f64 internal. 256 threads.
// ---------------------------------------------------------------------------
__device__ __forceinline__ void fft1024d(double2* a, int tid, bool inverse) {
    #pragma unroll
    for (int rep = 0; rep < 4; rep++) {
        int i = tid + rep * 256;
        int j = __brev(i) >> 22;
        if (j > i) { double2 t = a[i]; a[i] = a[j]; a[j] = t; }
    }
    __syncthreads();
    #pragma unroll
    for (int s = 0; s < 10; s++) {
        int half = 1 << s;
        #pragma unroll
        for (int rep = 0; rep < 2; rep++) {
            int w   = tid + rep * 256;
            int pos = w & (half - 1);
            int i0  = ((w >> s) << (s + 1)) + pos;
            int i1  = i0 + half;
            double2 t = g_twd[pos << (9 - s)];
            double ty = inverse ? -t.y : t.y;
            double2 u = a[i0], v = a[i1];
            double vr = v.x * t.x - v.y * ty;
            double vi = v.x * ty + v.y * t.x;
            a[i0] = make_double2(u.x + vr, u.y + vi);
            a[i1] = make_double2(u.x - vr, u.y - vi);
        }
        __syncthreads();
    }
}

// ---------------------------------------------------------------------------
// Bilinear tap weights, mimicking jax.image compute_weight_mat f32 arithmetic:
// per-tap weight w = fl(1 - fl(|p - h|)), out-of-range taps dropped, then
// normalized by fl(w0+w1) with f32 division.
// ---------------------------------------------------------------------------
__device__ __forceinline__ void lin_weights(float p, int in_size,
                                            int& i0, int& i1,
                                            float& w0, float& w1) {
    int h0 = (int)floorf(p);
    int h1 = h0 + 1;
    float x0 = __fsub_rn(p, (float)h0);
    float x1 = __fsub_rn((float)h1, p);
    float a0 = (h0 >= 0 && h0 < in_size) ? __fsub_rn(1.0f, x0) : 0.0f;
    float a1 = (h1 >= 0 && h1 < in_size) ? __fsub_rn(1.0f, x1) : 0.0f;
    float tot = __fadd_rn(a0, a1);
    w0 = __fdiv_rn(a0, tot);
    w1 = __fdiv_rn(a1, tot);
    i0 = min(in_size - 1, max(0, h0));
    i1 = min(in_size - 1, max(0, h1));
}

// ---------------------------------------------------------------------------
// full_spec: (32,64)->(128,512). Reference contracts H first, then W.
// ---------------------------------------------------------------------------
__global__ void k_fullspec(const float* __restrict__ params, float* __restrict__ fs) {
    int i = blockIdx.x * blockDim.x + threadIdx.x;
    if (i >= OUT_FS) return;
    int w = i & 511;
    int h = (i >> 9) & 127;
    int b = i >> 16;
    float py = __fsub_rn(__fmul_rn(__fadd_rn((float)h, 0.5f), 0.25f),  0.5f);
    float px = __fsub_rn(__fmul_rn(__fadd_rn((float)w, 0.5f), 0.125f), 0.5f);
    int y0, y1, x0, x1; float wy0, wy1, wx0, wx1;
    lin_weights(py, GH, y0, y1, wy0, wy1);
    lin_weights(px, GW, x0, x1, wx0, wx1);
    const float* g = params + b * (GH*GW);
    float v00 = g[y0*GW + x0], v01 = g[y0*GW + x1];
    float v10 = g[y1*GW + x0], v11 = g[y1*GW + x1];
    // H contraction first (rounded), then W
    float c0 = __fadd_rn(__fmul_rn(wy0, v00), __fmul_rn(wy1, v10));
    float c1 = __fadd_rn(__fmul_rn(wy0, v01), __fmul_rn(wy1, v11));
    fs[i] = __fadd_rn(__fmul_rn(wx0, c0), __fmul_rn(wx1, c1));
}

// ---------------------------------------------------------------------------
// mag = sqrt(max(resize_H(fl(fs^2)*100, 128->513), 0)), layout [b][f][k]
// ---------------------------------------------------------------------------
__global__ void k_mag(const float* __restrict__ fs) {
    int i = blockIdx.x * blockDim.x + threadIdx.x;
    if (i >= NTOT) return;
    int k  = i % NK;
    int bf = i / NK;
    int f  = bf & (NFRAMES - 1);
    int b  = bf >> 9;
    const float invs = (float)(128.0 / 513.0);
    float p = __fsub_rn(__fmul_rn(__fadd_rn((float)k, 0.5f), invs), 0.5f);
    int h0, h1; float w0, w1;
    lin_weights(p, FULL_H, h0, h1, w0, w1);
    const float* fb = fs + (size_t)b * (FULL_H * FULL_W);
    float a0 = fb[h0 * FULL_W + f];
    float a1 = fb[h1 * FULL_W + f];
    float sp0 = __fmul_rn(__fmul_rn(a0, a0), 100.0f);
    float sp1 = __fmul_rn(__fmul_rn(a1, a1), 100.0f);
    float v = __fadd_rn(__fmul_rn(w0, sp0), __fmul_rn(w1, sp1));
    g_mag[i] = sqrtf(fmaxf(v, 0.0f));
}

// ---------------------------------------------------------------------------
// Phase init. bits = out0 ^ out1 of threefry((0,1),(0,cnt)); u in [0,1);
// th = fl32(2pi)*u (f32); exact trig; S = fl(mag*cos), fl(mag*sin).
// ---------------------------------------------------------------------------
__global__ void k_init_phase() {
    int i = blockIdx.x * blockDim.x + threadIdx.x;
    if (i >= NTOT) return;
    int k  = i % NK;
    int bf = i / NK;
    int f  = bf & (NFRAMES - 1);
    int b  = bf >> 9;
    unsigned cnt = (unsigned)((b * NK + k) * NFRAMES + f);
    uint2 r = threefry_01(0u, cnt);
    unsigned bits = r.x ^ r.y;
    float u = __uint_as_float((bits >> 9) | 0x3f800000u) - 1.0f;
    float th = __fmul_rn(TWOPI_F, u);
    float cs = (float)cos((double)th);
    float sn = (float)sin((double)th);
    float m = g_mag[i];
    g_S[i] = make_float2(__fmul_rn(m, cs), __fmul_rn(m, sn));
    g_T[i] = make_float2(0.f, 0.f);
}

// ---------------------------------------------------------------------------
// ISTFT stage 1: irfft(S) (f64 internal) -> round f32 -> * win (f32)
// ---------------------------------------------------------------------------
__global__ void k_istft_frames() {
    int bf  = blockIdx.x;
    int tid = threadIdx.x;
    __shared__ double2 a[NFFT];
    const float2* Sp = g_S + (size_t)bf * NK;
    for (int k = tid; k < NK; k += 256) {
        float2 s = Sp[k];
        a[k] = make_double2((double)s.x, (double)s.y);
    }
    __syncthreads();
    for (int k = NK + tid; k < NFFT; k += 256) {
        double2 v = a[NFFT - k];
        a[k] = make_double2(v.x, -v.y);
    }
    __syncthreads();
    fft1024d(a, tid, true);
    float* fr = g_frames + (size_t)bf * NFFT;
    for (int n = tid; n < NFFT; n += 256) {
        float y = (float)(a[n].x * (1.0 / 1024.0));   // = reference irfft output
        fr[n] = __fmul_rn(y, g_win[n]);               // separate f32 rounding
    }
}

// ---------------------------------------------------------------------------
// ISTFT stage 2: OLA, f32 ascending-frame accumulation (mimics scatter-add)
// ---------------------------------------------------------------------------
__global__ void k_ola() {
    int i = blockIdx.x * blockDim.x + threadIdx.x;
    if (i >= GB * LSIG) return;
    int b  = i / LSIG;
    int tp = i - b * LSIG;
    int t  = tp + 512;
    int fhi = min(NFRAMES - 1, t >> 8);
    int flo = max(0, (t - 768) >> 8);
    const float* fr = g_frames + (size_t)b * NFRAMES * NFFT;
    float s = 0.f, w2 = 0.f;
    for (int f = flo; f <= fhi; f++) {
        int n = t - (f << 8);
        s  = __fadd_rn(s,  fr[(size_t)f * NFFT + n]);
        w2 = __fadd_rn(w2, g_win2[n]);
    }
    float den = (w2 > 1e-11f) ? w2 : 1.0f;
    g_audio[i] = __fdiv_rn(s, den);
}

// ---------------------------------------------------------------------------
// STFT (f64 FFT of f32-windowed frame) + GL update with exact f32 op order:
//   tmp = fl(c*tprev); A = fl(R - tmp); m = |A| (exact->f32); d = fl(m+1e-16)
//   an = fl(A/d); S = fl(mag*an); T = R
// ---------------------------------------------------------------------------
__global__ void k_stft_update() {
    int bf  = blockIdx.x;
    int f   = bf & (NFRAMES - 1);
    int b   = bf >> 9;
    int tid = threadIdx.x;
    __shared__ double2 a[NFFT];
    const float* au = g_audio + (size_t)b * LSIG;
    for (int n = tid; n < NFFT; n += 256) {
        int idx = (f << 8) + n - 512;
        if (idx < 0) idx = -idx;
        else if (idx >= LSIG) idx = 2 * LSIG - 2 - idx;
        float xv = __fmul_rn(au[idx], g_win[n]);
        a[n] = make_double2((double)xv, 0.0);
    }
    __syncthreads();
    fft1024d(a, tid, false);
    size_t base = (size_t)bf * NK;
    const float cmom = (float)(0.99 / 1.99);
    for (int k = tid; k < NK; k += 256) {
        float Rx = (float)a[k].x;
        float Ry = (float)a[k].y;
        float2 tp = g_T[base + k];
        float ax = __fsub_rn(Rx, __fmul_rn(cmom, tp.x));
        float ay = __fsub_rn(Ry, __fmul_rn(cmom, tp.y));
        double dm = sqrt((double)ax * (double)ax + (double)ay * (double)ay);
        float d = __fadd_rn((float)dm, 1e-16f);
        float anx = __fdiv_rn(ax, d);
        float any = __fdiv_rn(ay, d);
        float m = g_mag[base + k];
        g_S[base + k] = make_float2(__fmul_rn(m, anx), __fmul_rn(m, any));
        g_T[base + k] = make_float2(Rx, Ry);
    }
}

// ---------------------------------------------------------------------------
// Per-batch max |audio| (order-insensitive, exact)
// ---------------------------------------------------------------------------
__global__ void k_max() {
    int b   = blockIdx.x;
    int tid = threadIdx.x;
    __shared__ float red[1024];
    const float* au = g_audio + (size_t)b * LSIG;
    float m = 0.f;
    for (int i = tid; i < LSIG; i += 1024) m = fmaxf(m, fabsf(au[i]));
    red[tid] = m;
    __syncthreads();
    for (int s = 512; s > 0; s >>= 1) {
        if (tid < s) red[tid] = fmaxf(red[tid], red[tid + s]);
        __syncthreads();
    }
    if (tid == 0) g_maxv[b] = fmaxf(red[0], 1e-8f);
}

// ---------------------------------------------------------------------------
// Final: out = fl(fl(audio/max)*0.9), zero-padded to NSAMP
// ---------------------------------------------------------------------------
__global__ void k_final(float* __restrict__ out) {
    int i = blockIdx.x * blockDim.x + threadIdx.x;
    if (i >= OUT_AUDIO) return;
    int b = i >> 17;
    int t = i & (NSAMP - 1);
    float v = 0.f;
    if (t < LSIG)
        v = __fmul_rn(__fdiv_rn(g_audio[(size_t)b * LSIG + t], g_maxv[b]), 0.9f);
    out[i] = v;
}

// ---------------------------------------------------------------------------
extern "C" void kernel_launch(void* const* d_in, const int* in_sizes, int n_in,
                              void* d_out, int out_size) {
    const float* params = (const float*)d_in[0];
    float* out = (float*)d_out;
    float* fs_out = out + OUT_AUDIO;

    k_init_tables<<<4, 256>>>();
    k_fullspec<<<(OUT_FS + 255) / 256, 256>>>(params, fs_out);
    k_mag<<<(NTOT + 255) / 256, 256>>>(fs_out);
    k_init_phase<<<(NTOT + 255) / 256, 256>>>();

    const int NBF = GB * NFRAMES;
    for (int it = 0; it < 32; it++) {
        k_istft_frames<<<NBF, 256>>>();
        k_ola<<<(GB * LSIG + 255) / 256, 256>>>();
        k_stft_update<<<NBF, 256>>>();
    }
    k_istft_frames<<<NBF, 256>>>();
    k_ola<<<(GB * LSIG + 255) / 256, 256>>>();
    k_max<<<GB, 1024>>>();
    k_final<<<(OUT_AUDIO + 255) / 256, 256>>>(out);
}

// round 4
// speedup vs baseline: 1.5621x; 1.5621x over previous
#include <cuda_runtime.h>
#include <math.h>
#include <stdint.h>

#define GB       8
#define GH       32
#define GW       64
#define FULL_H   128
#define FULL_W   512
#define NFFT     1024
#define HOP      256
#define NK       513
#define NFRAMES  512
#define LSIG     130816
#define NSAMP    131072
#define NTOT     (GB*NFRAMES*NK)
#define OUT_AUDIO (GB*NSAMP)
#define OUT_FS    (GB*FULL_H*FULL_W)

#define TWOPI_F  6.28318548202514648438f   /* f32(2*pi) */

// ---------------------------------------------------------------------------
// Device scratch
// ---------------------------------------------------------------------------
__device__ float   g_win[NFFT];       // f32 hann, JAX rounding
__device__ float   g_win2[NFFT];      // fl(win*win)
__device__ double2 g_twd1024[NK];     // e^{-2pi i k/1024}, k=0..512 (f64 exact)
__device__ float   g_mag[NTOT];
__device__ float2  g_S[NTOT];
__device__ float2  g_T[NTOT];
__device__ float   g_frames[GB*NFRAMES*NFFT];
__device__ float   g_audio[GB*LSIG];
__device__ float   g_maxv[GB];

// ---------------------------------------------------------------------------
// Tables
// ---------------------------------------------------------------------------
__global__ void k_init_tables() {
    int i = blockIdx.x * blockDim.x + threadIdx.x;
    if (i < NFFT) {
        float af = __fdiv_rn(__fmul_rn(TWOPI_F, (float)i), 1024.0f);
        float c  = (float)cos((double)af);
        float w  = __fmul_rn(0.5f, __fsub_rn(1.0f, c));
        g_win[i]  = w;
        g_win2[i] = __fmul_rn(w, w);
    }
    if (i < NK) {
        double a = 2.0 * M_PI * (double)i / 1024.0;
        g_twd1024[i] = make_double2(cos(a), -sin(a));
    }
}

// ---------------------------------------------------------------------------
// threefry2x32, key (0,1)
// ---------------------------------------------------------------------------
__device__ __forceinline__ unsigned rotl32(unsigned x, int r) {
    return (x << r) | (x >> (32 - r));
}
__device__ __forceinline__ uint2 threefry_01(unsigned c0, unsigned c1) {
    const unsigned k0 = 0u, k1 = 1u;
    const unsigned k2 = 0x1BD11BDAu ^ k0 ^ k1;
    unsigned x0 = c0 + k0, x1 = c1 + k1;
#define TFR(r) { x0 += x1; x1 = rotl32(x1, (r)); x1 ^= x0; }
    TFR(13) TFR(15) TFR(26) TFR(6)
    x0 += k1; x1 += k2 + 1u;
    TFR(17) TFR(29) TFR(16) TFR(24)
    x0 += k2; x1 += k0 + 2u;
    TFR(13) TFR(15) TFR(26) TFR(6)
    x0 += k0; x1 += k1 + 3u;
    TFR(17) TFR(29) TFR(16) TFR(24)
    x0 += k1; x1 += k2 + 4u;
    TFR(13) TFR(15) TFR(26) TFR(6)
    x0 += k2; x1 += k0 + 5u;
#undef TFR
    return make_uint2(x0, x1);
}

// ---------------------------------------------------------------------------
// 512-pt complex FFT, f64, smem, 256 threads (1 butterfly/thread/stage).
// forward: e^{-2pi i}; inverse: e^{+2pi i}; both unnormalized.
// Twiddles from g_twd1024: e^{-2pi i q/512} = g_twd1024[2q].
// ---------------------------------------------------------------------------
__device__ __forceinline__ void fft512d(double2* a, int tid, bool inverse) {
    // 9-bit bit reversal, 2 elements per thread
    #pragma unroll
    for (int rep = 0; rep < 2; rep++) {
        int i = tid + rep * 256;
        int j = __brev(i) >> 23;
        if (j > i) { double2 t = a[i]; a[i] = a[j]; a[j] = t; }
    }
    __syncthreads();
    #pragma unroll
    for (int s = 0; s < 9; s++) {
        int half = 1 << s;
        int pos  = tid & (half - 1);
        int i0   = ((tid >> s) << (s + 1)) + pos;
        int i1   = i0 + half;
        double2 t = g_twd1024[pos << (9 - s)];
        double ty = inverse ? -t.y : t.y;
        double2 u = a[i0], v = a[i1];
        double vr = v.x * t.x - v.y * ty;
        double vi = v.x * ty + v.y * t.x;
        a[i0] = make_double2(u.x + vr, u.y + vi);
        a[i1] = make_double2(u.x - vr, u.y - vi);
        __syncthreads();
    }
}

// ---------------------------------------------------------------------------
// Bilinear tap weights (compute_weight_mat f32 mimicry)
// ---------------------------------------------------------------------------
__device__ __forceinline__ void lin_weights(float p, int in_size,
                                            int& i0, int& i1,
                                            float& w0, float& w1) {
    int h0 = (int)floorf(p);
    int h1 = h0 + 1;
    float x0 = __fsub_rn(p, (float)h0);
    float x1 = __fsub_rn((float)h1, p);
    float a0 = (h0 >= 0 && h0 < in_size) ? __fsub_rn(1.0f, x0) : 0.0f;
    float a1 = (h1 >= 0 && h1 < in_size) ? __fsub_rn(1.0f, x1) : 0.0f;
    float tot = __fadd_rn(a0, a1);
    w0 = __fdiv_rn(a0, tot);
    w1 = __fdiv_rn(a1, tot);
    i0 = min(in_size - 1, max(0, h0));
    i1 = min(in_size - 1, max(0, h1));
}

// ---------------------------------------------------------------------------
// full_spec: (32,64)->(128,512), H contraction first
// ---------------------------------------------------------------------------
__global__ void k_fullspec(const float* __restrict__ params, float* __restrict__ fs) {
    int i = blockIdx.x * blockDim.x + threadIdx.x;
    if (i >= OUT_FS) return;
    int w = i & 511;
    int h = (i >> 9) & 127;
    int b = i >> 16;
    float py = __fsub_rn(__fmul_rn(__fadd_rn((float)h, 0.5f), 0.25f),  0.5f);
    float px = __fsub_rn(__fmul_rn(__fadd_rn((float)w, 0.5f), 0.125f), 0.5f);
    int y0, y1, x0, x1; float wy0, wy1, wx0, wx1;
    lin_weights(py, GH, y0, y1, wy0, wy1);
    lin_weights(px, GW, x0, x1, wx0, wx1);
    const float* g = params + b * (GH*GW);
    float v00 = g[y0*GW + x0], v01 = g[y0*GW + x1];
    float v10 = g[y1*GW + x0], v11 = g[y1*GW + x1];
    float c0 = __fadd_rn(__fmul_rn(wy0, v00), __fmul_rn(wy1, v10));
    float c1 = __fadd_rn(__fmul_rn(wy0, v01), __fmul_rn(wy1, v11));
    fs[i] = __fadd_rn(__fmul_rn(wx0, c0), __fmul_rn(wx1, c1));
}

// ---------------------------------------------------------------------------
// mag = sqrt(max(resize_H(fl(fs^2)*100, 128->513), 0)), layout [b][f][k]
// ---------------------------------------------------------------------------
__global__ void k_mag(const float* __restrict__ fs) {
    int i = blockIdx.x * blockDim.x + threadIdx.x;
    if (i >= NTOT) return;
    int k  = i % NK;
    int bf = i / NK;
    int f  = bf & (NFRAMES - 1);
    int b  = bf >> 9;
    const float invs = (float)(128.0 / 513.0);
    float p = __fsub_rn(__fmul_rn(__fadd_rn((float)k, 0.5f), invs), 0.5f);
    int h0, h1; float w0, w1;
    lin_weights(p, FULL_H, h0, h1, w0, w1);
    const float* fb = fs + (size_t)b * (FULL_H * FULL_W);
    float a0 = fb[h0 * FULL_W + f];
    float a1 = fb[h1 * FULL_W + f];
    float sp0 = __fmul_rn(__fmul_rn(a0, a0), 100.0f);
    float sp1 = __fmul_rn(__fmul_rn(a1, a1), 100.0f);
    float v = __fadd_rn(__fmul_rn(w0, sp0), __fmul_rn(w1, sp1));
    g_mag[i] = sqrtf(fmaxf(v, 0.0f));
}

// ---------------------------------------------------------------------------
// Phase init (threefry partitionable: bits = out0 ^ out1)
// ---------------------------------------------------------------------------
__global__ void k_init_phase() {
    int i = blockIdx.x * blockDim.x + threadIdx.x;
    if (i >= NTOT) return;
    int k  = i % NK;
    int bf = i / NK;
    int f  = bf & (NFRAMES - 1);
    int b  = bf >> 9;
    unsigned cnt = (unsigned)((b * NK + k) * NFRAMES + f);
    uint2 r = threefry_01(0u, cnt);
    unsigned bits = r.x ^ r.y;
    float u = __uint_as_float((bits >> 9) | 0x3f800000u) - 1.0f;
    float th = __fmul_rn(TWOPI_F, u);
    float cs = (float)cos((double)th);
    float sn = (float)sin((double)th);
    float m = g_mag[i];
    g_S[i] = make_float2(__fmul_rn(m, cs), __fmul_rn(m, sn));
    g_T[i] = make_float2(0.f, 0.f);
}

// ---------------------------------------------------------------------------
// ISTFT: irfft via 512-pt complex IFFT (real-FFT packing), then * win (f32).
// C[k] = (X[k]+conj(X[512-k])) + i*e^{+2pi i k/1024}*(X[k]-conj(X[512-k]))
// y[m] = (1/1024) * IFFT512_unnorm(C)[m];  x[2m]=Re y, x[2m+1]=Im y.
// Imag of bins 0 and 512 dropped (pocketfft c2r semantics).
// ---------------------------------------------------------------------------
__global__ void k_istft_frames() {
    int bf  = blockIdx.x;
    int tid = threadIdx.x;
    __shared__ double2 a[512];
    const float2* Sp = g_S + (size_t)bf * NK;
    #pragma unroll
    for (int rep = 0; rep < 2; rep++) {
        int k = tid + rep * 256;
        float2 xk = Sp[k];
        float2 xm = Sp[512 - k];
        double xky = (k == 0) ? 0.0 : (double)xk.y;
        double xmy = (k == 0) ? 0.0 : (double)xm.y;
        double Sx = (double)xk.x + (double)xm.x;
        double Sy = xky - xmy;
        double Dx = (double)xk.x - (double)xm.x;
        double Dy = xky + xmy;
        double2 t = g_twd1024[k];          // u = conj(t) = (t.x, -t.y)
        a[k] = make_double2(Sx - t.x * Dy + t.y * Dx,
                            Sy + t.x * Dx + t.y * Dy);
    }
    __syncthreads();
    fft512d(a, tid, true);
    float2* fr = (float2*)(g_frames + (size_t)bf * NFFT);
    #pragma unroll
    for (int rep = 0; rep < 2; rep++) {
        int m = tid + rep * 256;
        double2 ym = a[m];
        float y0 = (float)(ym.x * (1.0 / 1024.0));
        float y1 = (float)(ym.y * (1.0 / 1024.0));
        fr[m] = make_float2(__fmul_rn(y0, g_win[2*m]),
                            __fmul_rn(y1, g_win[2*m + 1]));
    }
}

// ---------------------------------------------------------------------------
// OLA: f32 ascending-frame accumulation + wsq normalization
// ---------------------------------------------------------------------------
__global__ void k_ola() {
    int i = blockIdx.x * blockDim.x + threadIdx.x;
    if (i >= GB * LSIG) return;
    int b  = i / LSIG;
    int tp = i - b * LSIG;
    int t  = tp + 512;
    int fhi = min(NFRAMES - 1, t >> 8);
    int flo = max(0, (t - 768) >> 8);
    const float* fr = g_frames + (size_t)b * NFRAMES * NFFT;
    float s = 0.f, w2 = 0.f;
    for (int f = flo; f <= fhi; f++) {
        int n = t - (f << 8);
        s  = __fadd_rn(s,  fr[(size_t)f * NFFT + n]);
        w2 = __fadd_rn(w2, g_win2[n]);
    }
    float den = (w2 > 1e-11f) ? w2 : 1.0f;
    g_audio[i] = __fdiv_rn(s, den);
}

// ---------------------------------------------------------------------------
// STFT via 512-pt complex FFT (real packing) + GL momentum update (f32 mimicry).
// X[k] = 0.5*(Y[k]+conj(Y[(512-k)&511])) - 0.5*i*t_k*(Y[k]-conj(Y[(512-k)&511]))
// ---------------------------------------------------------------------------
__global__ void k_stft_update() {
    int bf  = blockIdx.x;
    int f   = bf & (NFRAMES - 1);
    int b   = bf >> 9;
    int tid = threadIdx.x;
    __shared__ double2 a[512];
    const float* au = g_audio + (size_t)b * LSIG;
    #pragma unroll
    for (int rep = 0; rep < 2; rep++) {
        int m = tid + rep * 256;
        int n0 = 2 * m, n1 = 2 * m + 1;
        int i0 = (f << 8) + n0 - 512;
        int i1 = i0 + 1;
        if (i0 < 0) i0 = -i0; else if (i0 >= LSIG) i0 = 2 * LSIG - 2 - i0;
        if (i1 < 0) i1 = -i1; else if (i1 >= LSIG) i1 = 2 * LSIG - 2 - i1;
        float xv0 = __fmul_rn(au[i0], g_win[n0]);
        float xv1 = __fmul_rn(au[i1], g_win[n1]);
        a[m] = make_double2((double)xv0, (double)xv1);
    }
    __syncthreads();
    fft512d(a, tid, false);
    size_t base = (size_t)bf * NK;
    const float cmom = (float)(0.99 / 1.99);
    for (int k = tid; k < NK; k += 256) {
        int m1 = (512 - k) & 511;
        double2 P = a[k & 511];
        double2 Q = a[m1];                  // conj applied below
        double Sx = P.x + Q.x, Sy = P.y - Q.y;
        double Dx = P.x - Q.x, Dy = P.y + Q.y;
        double2 t = g_twd1024[k];
        float Rx = (float)(0.5 * (Sx + t.x * Dy + t.y * Dx));
        float Ry = (float)(0.5 * (Sy - (t.x * Dx - t.y * Dy)));
        float2 tp = g_T[base + k];
        float ax = __fsub_rn(Rx, __fmul_rn(cmom, tp.x));
        float ay = __fsub_rn(Ry, __fmul_rn(cmom, tp.y));
        double dm = sqrt((double)ax * (double)ax + (double)ay * (double)ay);
        float d = __fadd_rn((float)dm, 1e-16f);
        float anx = __fdiv_rn(ax, d);
        float any = __fdiv_rn(ay, d);
        float m = g_mag[base + k];
        g_S[base + k] = make_float2(__fmul_rn(m, anx), __fmul_rn(m, any));
        g_T[base + k] = make_float2(Rx, Ry);
    }
}

// ---------------------------------------------------------------------------
__global__ void k_max() {
    int b   = blockIdx.x;
    int tid = threadIdx.x;
    __shared__ float red[1024];
    const float* au = g_audio + (size_t)b * LSIG;
    float m = 0.f;
    for (int i = tid; i < LSIG; i += 1024) m = fmaxf(m, fabsf(au[i]));
    red[tid] = m;
    __syncthreads();
    for (int s = 512; s > 0; s >>= 1) {
        if (tid < s) red[tid] = fmaxf(red[tid], red[tid + s]);
        __syncthreads();
    }
    if (tid == 0) g_maxv[b] = fmaxf(red[0], 1e-8f);
}

__global__ void k_final(float* __restrict__ out) {
    int i = blockIdx.x * blockDim.x + threadIdx.x;
    if (i >= OUT_AUDIO) return;
    int b = i >> 17;
    int t = i & (NSAMP - 1);
    float v = 0.f;
    if (t < LSIG)
        v = __fmul_rn(__fdiv_rn(g_audio[(size_t)b * LSIG + t], g_maxv[b]), 0.9f);
    out[i] = v;
}

// ---------------------------------------------------------------------------
extern "C" void kernel_launch(void* const* d_in, const int* in_sizes, int n_in,
                              void* d_out, int out_size) {
    const float* params = (const float*)d_in[0];
    float* out = (float*)d_out;
    float* fs_out = out + OUT_AUDIO;

    k_init_tables<<<4, 256>>>();
    k_fullspec<<<(OUT_FS + 255) / 256, 256>>>(params, fs_out);
    k_mag<<<(NTOT + 255) / 256, 256>>>(fs_out);
    k_init_phase<<<(NTOT + 255) / 256, 256>>>();

    const int NBF = GB * NFRAMES;
    for (int it = 0; it < 32; it++) {
        k_istft_frames<<<NBF, 256>>>();
        k_ola<<<(GB * LSIG + 255) / 256, 256>>>();
        k_stft_update<<<NBF, 256>>>();
    }
    k_istft_frames<<<NBF, 256>>>();
    k_ola<<<(GB * LSIG + 255) / 256, 256>>>();
    k_max<<<GB, 1024>>>();
    k_final<<<(OUT_AUDIO + 255) / 256, 256>>>(out);
}

// round 5
// speedup vs baseline: 2.5417x; 1.6271x over previous
#include <cuda_runtime.h>
#include <math.h>
#include <stdint.h>

#define GB       8
#define GH       32
#define GW       64
#define FULL_H   128
#define FULL_W   512
#define NFFT     1024
#define HOP      256
#define NK       513
#define NFRAMES  512
#define LSIG     130816
#define NSAMP    131072
#define NTOT     (GB*NFRAMES*NK)
#define OUT_AUDIO (GB*NSAMP)
#define OUT_FS    (GB*FULL_H*FULL_W)

#define N_F64_ITERS 16   /* GL iterations done in f64; rest in f32 */

#define TWOPI_F  6.28318548202514648438f   /* f32(2*pi) */

// ---------------------------------------------------------------------------
// Device scratch
// ---------------------------------------------------------------------------
__device__ float   g_win[NFFT];
__device__ float   g_win2[NFFT];
__device__ double2 g_twd1024[NK];     // e^{-2pi i k/1024} f64
__device__ float2  g_twdf1024[NK];    // f32 copy
__device__ float   g_mag[NTOT];
__device__ float2  g_S[NTOT];
__device__ float2  g_T[NTOT];
__device__ float   g_frames[GB*NFRAMES*NFFT];
__device__ float   g_audio[GB*LSIG];
__device__ float   g_maxv[GB];

// ---------------------------------------------------------------------------
__global__ void k_init_tables() {
    int i = blockIdx.x * blockDim.x + threadIdx.x;
    if (i < NFFT) {
        float af = __fdiv_rn(__fmul_rn(TWOPI_F, (float)i), 1024.0f);
        float c  = (float)cos((double)af);
        float w  = __fmul_rn(0.5f, __fsub_rn(1.0f, c));
        g_win[i]  = w;
        g_win2[i] = __fmul_rn(w, w);
    }
    if (i < NK) {
        double a = 2.0 * M_PI * (double)i / 1024.0;
        double2 t = make_double2(cos(a), -sin(a));
        g_twd1024[i]  = t;
        g_twdf1024[i] = make_float2((float)t.x, (float)t.y);
    }
}

// ---------------------------------------------------------------------------
// threefry2x32, key (0,1)
// ---------------------------------------------------------------------------
__device__ __forceinline__ unsigned rotl32(unsigned x, int r) {
    return (x << r) | (x >> (32 - r));
}
__device__ __forceinline__ uint2 threefry_01(unsigned c0, unsigned c1) {
    const unsigned k0 = 0u, k1 = 1u;
    const unsigned k2 = 0x1BD11BDAu ^ k0 ^ k1;
    unsigned x0 = c0 + k0, x1 = c1 + k1;
#define TFR(r) { x0 += x1; x1 = rotl32(x1, (r)); x1 ^= x0; }
    TFR(13) TFR(15) TFR(26) TFR(6)
    x0 += k1; x1 += k2 + 1u;
    TFR(17) TFR(29) TFR(16) TFR(24)
    x0 += k2; x1 += k0 + 2u;
    TFR(13) TFR(15) TFR(26) TFR(6)
    x0 += k0; x1 += k1 + 3u;
    TFR(17) TFR(29) TFR(16) TFR(24)
    x0 += k1; x1 += k2 + 4u;
    TFR(13) TFR(15) TFR(26) TFR(6)
    x0 += k2; x1 += k0 + 5u;
#undef TFR
    return make_uint2(x0, x1);
}

// ---------------------------------------------------------------------------
// 512-pt complex FFT, f64, 256 threads
// ---------------------------------------------------------------------------
__device__ __forceinline__ void fft512d(double2* a, int tid, bool inverse) {
    #pragma unroll
    for (int rep = 0; rep < 2; rep++) {
        int i = tid + rep * 256;
        int j = __brev(i) >> 23;
        if (j > i) { double2 t = a[i]; a[i] = a[j]; a[j] = t; }
    }
    __syncthreads();
    #pragma unroll
    for (int s = 0; s < 9; s++) {
        int half = 1 << s;
        int pos  = tid & (half - 1);
        int i0   = ((tid >> s) << (s + 1)) + pos;
        int i1   = i0 + half;
        double2 t = g_twd1024[pos << (9 - s)];
        double ty = inverse ? -t.y : t.y;
        double2 u = a[i0], v = a[i1];
        double vr = v.x * t.x - v.y * ty;
        double vi = v.x * ty + v.y * t.x;
        a[i0] = make_double2(u.x + vr, u.y + vi);
        a[i1] = make_double2(u.x - vr, u.y - vi);
        __syncthreads();
    }
}

// ---------------------------------------------------------------------------
// 512-pt complex FFT, f32, 256 threads
// ---------------------------------------------------------------------------
__device__ __forceinline__ void fft512f(float2* a, int tid, bool inverse) {
    #pragma unroll
    for (int rep = 0; rep < 2; rep++) {
        int i = tid + rep * 256;
        int j = __brev(i) >> 23;
        if (j > i) { float2 t = a[i]; a[i] = a[j]; a[j] = t; }
    }
    __syncthreads();
    #pragma unroll
    for (int s = 0; s < 9; s++) {
        int half = 1 << s;
        int pos  = tid & (half - 1);
        int i0   = ((tid >> s) << (s + 1)) + pos;
        int i1   = i0 + half;
        float2 t = g_twdf1024[pos << (9 - s)];
        float ty = inverse ? -t.y : t.y;
        float2 u = a[i0], v = a[i1];
        float vr = v.x * t.x - v.y * ty;
        float vi = v.x * ty + v.y * t.x;
        a[i0] = make_float2(u.x + vr, u.y + vi);
        a[i1] = make_float2(u.x - vr, u.y - vi);
        __syncthreads();
    }
}

// ---------------------------------------------------------------------------
// Bilinear tap weights (compute_weight_mat f32 mimicry)
// ---------------------------------------------------------------------------
__device__ __forceinline__ void lin_weights(float p, int in_size,
                                            int& i0, int& i1,
                                            float& w0, float& w1) {
    int h0 = (int)floorf(p);
    int h1 = h0 + 1;
    float x0 = __fsub_rn(p, (float)h0);
    float x1 = __fsub_rn((float)h1, p);
    float a0 = (h0 >= 0 && h0 < in_size) ? __fsub_rn(1.0f, x0) : 0.0f;
    float a1 = (h1 >= 0 && h1 < in_size) ? __fsub_rn(1.0f, x1) : 0.0f;
    float tot = __fadd_rn(a0, a1);
    w0 = __fdiv_rn(a0, tot);
    w1 = __fdiv_rn(a1, tot);
    i0 = min(in_size - 1, max(0, h0));
    i1 = min(in_size - 1, max(0, h1));
}

__global__ void k_fullspec(const float* __restrict__ params, float* __restrict__ fs) {
    int i = blockIdx.x * blockDim.x + threadIdx.x;
    if (i >= OUT_FS) return;
    int w = i & 511;
    int h = (i >> 9) & 127;
    int b = i >> 16;
    float py = __fsub_rn(__fmul_rn(__fadd_rn((float)h, 0.5f), 0.25f),  0.5f);
    float px = __fsub_rn(__fmul_rn(__fadd_rn((float)w, 0.5f), 0.125f), 0.5f);
    int y0, y1, x0, x1; float wy0, wy1, wx0, wx1;
    lin_weights(py, GH, y0, y1, wy0, wy1);
    lin_weights(px, GW, x0, x1, wx0, wx1);
    const float* g = params + b * (GH*GW);
    float v00 = g[y0*GW + x0], v01 = g[y0*GW + x1];
    float v10 = g[y1*GW + x0], v11 = g[y1*GW + x1];
    float c0 = __fadd_rn(__fmul_rn(wy0, v00), __fmul_rn(wy1, v10));
    float c1 = __fadd_rn(__fmul_rn(wy0, v01), __fmul_rn(wy1, v11));
    fs[i] = __fadd_rn(__fmul_rn(wx0, c0), __fmul_rn(wx1, c1));
}

__global__ void k_mag(const float* __restrict__ fs) {
    int i = blockIdx.x * blockDim.x + threadIdx.x;
    if (i >= NTOT) return;
    int k  = i % NK;
    int bf = i / NK;
    int f  = bf & (NFRAMES - 1);
    int b  = bf >> 9;
    const float invs = (float)(128.0 / 513.0);
    float p = __fsub_rn(__fmul_rn(__fadd_rn((float)k, 0.5f), invs), 0.5f);
    int h0, h1; float w0, w1;
    lin_weights(p, FULL_H, h0, h1, w0, w1);
    const float* fb = fs + (size_t)b * (FULL_H * FULL_W);
    float a0 = fb[h0 * FULL_W + f];
    float a1 = fb[h1 * FULL_W + f];
    float sp0 = __fmul_rn(__fmul_rn(a0, a0), 100.0f);
    float sp1 = __fmul_rn(__fmul_rn(a1, a1), 100.0f);
    float v = __fadd_rn(__fmul_rn(w0, sp0), __fmul_rn(w1, sp1));
    g_mag[i] = sqrtf(fmaxf(v, 0.0f));
}

__global__ void k_init_phase() {
    int i = blockIdx.x * blockDim.x + threadIdx.x;
    if (i >= NTOT) return;
    int k  = i % NK;
    int bf = i / NK;
    int f  = bf & (NFRAMES - 1);
    int b  = bf >> 9;
    unsigned cnt = (unsigned)((b * NK + k) * NFRAMES + f);
    uint2 r = threefry_01(0u, cnt);
    unsigned bits = r.x ^ r.y;
    float u = __uint_as_float((bits >> 9) | 0x3f800000u) - 1.0f;
    float th = __fmul_rn(TWOPI_F, u);
    float cs = (float)cos((double)th);
    float sn = (float)sin((double)th);
    float m = g_mag[i];
    g_S[i] = make_float2(__fmul_rn(m, cs), __fmul_rn(m, sn));
    g_T[i] = make_float2(0.f, 0.f);
}

// ---------------------------------------------------------------------------
// ISTFT (f64): irfft via 512-pt complex IFFT (real packing), * win (f32)
// ---------------------------------------------------------------------------
__global__ void k_istft_frames() {
    int bf  = blockIdx.x;
    int tid = threadIdx.x;
    __shared__ double2 a[512];
    const float2* Sp = g_S + (size_t)bf * NK;
    #pragma unroll
    for (int rep = 0; rep < 2; rep++) {
        int k = tid + rep * 256;
        float2 xk = Sp[k];
        float2 xm = Sp[512 - k];
        double xky = (k == 0) ? 0.0 : (double)xk.y;
        double xmy = (k == 0) ? 0.0 : (double)xm.y;
        double Sx = (double)xk.x + (double)xm.x;
        double Sy = xky - xmy;
        double Dx = (double)xk.x - (double)xm.x;
        double Dy = xky + xmy;
        double2 t = g_twd1024[k];
        a[k] = make_double2(Sx - t.x * Dy + t.y * Dx,
                            Sy + t.x * Dx + t.y * Dy);
    }
    __syncthreads();
    fft512d(a, tid, true);
    float2* fr = (float2*)(g_frames + (size_t)bf * NFFT);
    #pragma unroll
    for (int rep = 0; rep < 2; rep++) {
        int m = tid + rep * 256;
        double2 ym = a[m];
        float y0 = (float)(ym.x * (1.0 / 1024.0));
        float y1 = (float)(ym.y * (1.0 / 1024.0));
        fr[m] = make_float2(__fmul_rn(y0, g_win[2*m]),
                            __fmul_rn(y1, g_win[2*m + 1]));
    }
}

// ---------------------------------------------------------------------------
// ISTFT (f32 variant)
// ---------------------------------------------------------------------------
__global__ void k_istft_frames_f32() {
    int bf  = blockIdx.x;
    int tid = threadIdx.x;
    __shared__ float2 a[512];
    const float2* Sp = g_S + (size_t)bf * NK;
    #pragma unroll
    for (int rep = 0; rep < 2; rep++) {
        int k = tid + rep * 256;
        float2 xk = Sp[k];
        float2 xm = Sp[512 - k];
        float xky = (k == 0) ? 0.0f : xk.y;
        float xmy = (k == 0) ? 0.0f : xm.y;
        float Sx = xk.x + xm.x;
        float Sy = xky - xmy;
        float Dx = xk.x - xm.x;
        float Dy = xky + xmy;
        float2 t = g_twdf1024[k];
        a[k] = make_float2(Sx - t.x * Dy + t.y * Dx,
                           Sy + t.x * Dx + t.y * Dy);
    }
    __syncthreads();
    fft512f(a, tid, true);
    float2* fr = (float2*)(g_frames + (size_t)bf * NFFT);
    #pragma unroll
    for (int rep = 0; rep < 2; rep++) {
        int m = tid + rep * 256;
        float2 ym = a[m];
        float y0 = ym.x * (1.0f / 1024.0f);   // exact power-of-2 scale
        float y1 = ym.y * (1.0f / 1024.0f);
        fr[m] = make_float2(__fmul_rn(y0, g_win[2*m]),
                            __fmul_rn(y1, g_win[2*m + 1]));
    }
}

// ---------------------------------------------------------------------------
// OLA
// ---------------------------------------------------------------------------
__global__ void k_ola() {
    int i = blockIdx.x * blockDim.x + threadIdx.x;
    if (i >= GB * LSIG) return;
    int b  = i / LSIG;
    int tp = i - b * LSIG;
    int t  = tp + 512;
    int fhi = min(NFRAMES - 1, t >> 8);
    int flo = max(0, (t - 768) >> 8);
    const float* fr = g_frames + (size_t)b * NFRAMES * NFFT;
    float s = 0.f, w2 = 0.f;
    for (int f = flo; f <= fhi; f++) {
        int n = t - (f << 8);
        s  = __fadd_rn(s,  fr[(size_t)f * NFFT + n]);
        w2 = __fadd_rn(w2, g_win2[n]);
    }
    float den = (w2 > 1e-11f) ? w2 : 1.0f;
    g_audio[i] = __fdiv_rn(s, den);
}

// ---------------------------------------------------------------------------
// STFT + GL update (f64 FFT)
// ---------------------------------------------------------------------------
__global__ void k_stft_update() {
    int bf  = blockIdx.x;
    int f   = bf & (NFRAMES - 1);
    int b   = bf >> 9;
    int tid = threadIdx.x;
    __shared__ double2 a[512];
    const float* au = g_audio + (size_t)b * LSIG;
    #pragma unroll
    for (int rep = 0; rep < 2; rep++) {
        int m = tid + rep * 256;
        int n0 = 2 * m, n1 = 2 * m + 1;
        int i0 = (f << 8) + n0 - 512;
        int i1 = i0 + 1;
        if (i0 < 0) i0 = -i0; else if (i0 >= LSIG) i0 = 2 * LSIG - 2 - i0;
        if (i1 < 0) i1 = -i1; else if (i1 >= LSIG) i1 = 2 * LSIG - 2 - i1;
        float xv0 = __fmul_rn(au[i0], g_win[n0]);
        float xv1 = __fmul_rn(au[i1], g_win[n1]);
        a[m] = make_double2((double)xv0, (double)xv1);
    }
    __syncthreads();
    fft512d(a, tid, false);
    size_t base = (size_t)bf * NK;
    const float cmom = (float)(0.99 / 1.99);
    for (int k = tid; k < NK; k += 256) {
        int m1 = (512 - k) & 511;
        double2 P = a[k & 511];
        double2 Q = a[m1];
        double Sx = P.x + Q.x, Sy = P.y - Q.y;
        double Dx = P.x - Q.x, Dy = P.y + Q.y;
        double2 t = g_twd1024[k];
        float Rx = (float)(0.5 * (Sx + t.x * Dy + t.y * Dx));
        float Ry = (float)(0.5 * (Sy - (t.x * Dx - t.y * Dy)));
        float2 tp = g_T[base + k];
        float ax = __fsub_rn(Rx, __fmul_rn(cmom, tp.x));
        float ay = __fsub_rn(Ry, __fmul_rn(cmom, tp.y));
        double dm = sqrt((double)ax * (double)ax + (double)ay * (double)ay);
        float d = __fadd_rn((float)dm, 1e-16f);
        float anx = __fdiv_rn(ax, d);
        float any = __fdiv_rn(ay, d);
        float m = g_mag[base + k];
        g_S[base + k] = make_float2(__fmul_rn(m, anx), __fmul_rn(m, any));
        g_T[base + k] = make_float2(Rx, Ry);
    }
}

// ---------------------------------------------------------------------------
// STFT + GL update (f32 FFT variant)
// ---------------------------------------------------------------------------
__global__ void k_stft_update_f32() {
    int bf  = blockIdx.x;
    int f   = bf & (NFRAMES - 1);
    int b   = bf >> 9;
    int tid = threadIdx.x;
    __shared__ float2 a[512];
    const float* au = g_audio + (size_t)b * LSIG;
    #pragma unroll
    for (int rep = 0; rep < 2; rep++) {
        int m = tid + rep * 256;
        int n0 = 2 * m, n1 = 2 * m + 1;
        int i0 = (f << 8) + n0 - 512;
        int i1 = i0 + 1;
        if (i0 < 0) i0 = -i0; else if (i0 >= LSIG) i0 = 2 * LSIG - 2 - i0;
        if (i1 < 0) i1 = -i1; else if (i1 >= LSIG) i1 = 2 * LSIG - 2 - i1;
        float xv0 = __fmul_rn(au[i0], g_win[n0]);
        float xv1 = __fmul_rn(au[i1], g_win[n1]);
        a[m] = make_float2(xv0, xv1);
    }
    __syncthreads();
    fft512f(a, tid, false);
    size_t base = (size_t)bf * NK;
    const float cmom = (float)(0.99 / 1.99);
    for (int k = tid; k < NK; k += 256) {
        int m1 = (512 - k) & 511;
        float2 P = a[k & 511];
        float2 Q = a[m1];
        float Sx = P.x + Q.x, Sy = P.y - Q.y;
        float Dx = P.x - Q.x, Dy = P.y + Q.y;
        float2 t = g_twdf1024[k];
        float Rx = 0.5f * (Sx + t.x * Dy + t.y * Dx);
        float Ry = 0.5f * (Sy - (t.x * Dx - t.y * Dy));
        float2 tp = g_T[base + k];
        float ax = __fsub_rn(Rx, __fmul_rn(cmom, tp.x));
        float ay = __fsub_rn(Ry, __fmul_rn(cmom, tp.y));
        double dm = sqrt((double)ax * (double)ax + (double)ay * (double)ay);
        float d = __fadd_rn((float)dm, 1e-16f);
        float anx = __fdiv_rn(ax, d);
        float any = __fdiv_rn(ay, d);
        float m = g_mag[base + k];
        g_S[base + k] = make_float2(__fmul_rn(m, anx), __fmul_rn(m, any));
        g_T[base + k] = make_float2(Rx, Ry);
    }
}

// ---------------------------------------------------------------------------
__global__ void k_max() {
    int b   = blockIdx.x;
    int tid = threadIdx.x;
    __shared__ float red[1024];
    const float* au = g_audio + (size_t)b * LSIG;
    float m = 0.f;
    for (int i = tid; i < LSIG; i += 1024) m = fmaxf(m, fabsf(au[i]));
    red[tid] = m;
    __syncthreads();
    for (int s = 512; s > 0; s >>= 1) {
        if (tid < s) red[tid] = fmaxf(red[tid], red[tid + s]);
        __syncthreads();
    }
    if (tid == 0) g_maxv[b] = fmaxf(red[0], 1e-8f);
}

__global__ void k_final(float* __restrict__ out) {
    int i = blockIdx.x * blockDim.x + threadIdx.x;
    if (i >= OUT_AUDIO) return;
    int b = i >> 17;
    int t = i & (NSAMP - 1);
    float v = 0.f;
    if (t < LSIG)
        v = __fmul_rn(__fdiv_rn(g_audio[(size_t)b * LSIG + t], g_maxv[b]), 0.9f);
    out[i] = v;
}

// ---------------------------------------------------------------------------
extern "C" void kernel_launch(void* const* d_in, const int* in_sizes, int n_in,
                              void* d_out, int out_size) {
    const float* params = (const float*)d_in[0];
    float* out = (float*)d_out;
    float* fs_out = out + OUT_AUDIO;

    k_init_tables<<<4, 256>>>();
    k_fullspec<<<(OUT_FS + 255) / 256, 256>>>(params, fs_out);
    k_mag<<<(NTOT + 255) / 256, 256>>>(fs_out);
    k_init_phase<<<(NTOT + 255) / 256, 256>>>();

    const int NBF = GB * NFRAMES;
    for (int it = 0; it < 32; it++) {
        if (it < N_F64_ITERS) {
            k_istft_frames<<<NBF, 256>>>();
            k_ola<<<(GB * LSIG + 255) / 256, 256>>>();
            k_stft_update<<<NBF, 256>>>();
        } else {
            k_istft_frames_f32<<<NBF, 256>>>();
            k_ola<<<(GB * LSIG + 255) / 256, 256>>>();
            k_stft_update_f32<<<NBF, 256>>>();
        }
    }
    k_istft_frames_f32<<<NBF, 256>>>();
    k_ola<<<(GB * LSIG + 255) / 256, 256>>>();
    k_max<<<GB, 1024>>>();
    k_final<<<(OUT_AUDIO + 255) / 256, 256>>>(out);
}

// round 6
// speedup vs baseline: 4.7334x; 1.8623x over previous
#include <cuda_runtime.h>
#include <math.h>
#include <stdint.h>

#define GB       8
#define GH       32
#define GW       64
#define FULL_H   128
#define FULL_W   512
#define NFFT     1024
#define HOP      256
#define NK       513
#define NFRAMES  512
#define LSIG     130816
#define NSAMP    131072
#define NTOT     (GB*NFRAMES*NK)
#define OUT_AUDIO (GB*NSAMP)
#define OUT_FS    (GB*FULL_H*FULL_W)

#define N_F64_ITERS 4    /* GL iterations done in f64; rest in f32 */

#define TWOPI_F  6.28318548202514648438f   /* f32(2*pi) */

// ---------------------------------------------------------------------------
// Device scratch
// ---------------------------------------------------------------------------
__device__ float   g_win[NFFT];
__device__ float   g_win2[NFFT];
__device__ double2 g_twd1024[NK];     // e^{-2pi i k/1024} f64
__device__ float2  g_twdf1024[NK];    // f32 copy
__device__ float   g_mag[NTOT];
__device__ float2  g_S[NTOT];
__device__ float2  g_T[NTOT];
__device__ float   g_frames[GB*NFRAMES*NFFT];
__device__ float   g_audio[GB*LSIG];
__device__ float   g_maxv[GB];

// ---------------------------------------------------------------------------
__global__ void k_init_tables() {
    int i = blockIdx.x * blockDim.x + threadIdx.x;
    if (i < NFFT) {
        float af = __fdiv_rn(__fmul_rn(TWOPI_F, (float)i), 1024.0f);
        float c  = (float)cos((double)af);
        float w  = __fmul_rn(0.5f, __fsub_rn(1.0f, c));
        g_win[i]  = w;
        g_win2[i] = __fmul_rn(w, w);
    }
    if (i < NK) {
        double a = 2.0 * M_PI * (double)i / 1024.0;
        double2 t = make_double2(cos(a), -sin(a));
        g_twd1024[i]  = t;
        g_twdf1024[i] = make_float2((float)t.x, (float)t.y);
    }
}

// ---------------------------------------------------------------------------
// threefry2x32, key (0,1)
// ---------------------------------------------------------------------------
__device__ __forceinline__ unsigned rotl32(unsigned x, int r) {
    return (x << r) | (x >> (32 - r));
}
__device__ __forceinline__ uint2 threefry_01(unsigned c0, unsigned c1) {
    const unsigned k0 = 0u, k1 = 1u;
    const unsigned k2 = 0x1BD11BDAu ^ k0 ^ k1;
    unsigned x0 = c0 + k0, x1 = c1 + k1;
#define TFR(r) { x0 += x1; x1 = rotl32(x1, (r)); x1 ^= x0; }
    TFR(13) TFR(15) TFR(26) TFR(6)
    x0 += k1; x1 += k2 + 1u;
    TFR(17) TFR(29) TFR(16) TFR(24)
    x0 += k2; x1 += k0 + 2u;
    TFR(13) TFR(15) TFR(26) TFR(6)
    x0 += k0; x1 += k1 + 3u;
    TFR(17) TFR(29) TFR(16) TFR(24)
    x0 += k1; x1 += k2 + 4u;
    TFR(13) TFR(15) TFR(26) TFR(6)
    x0 += k2; x1 += k0 + 5u;
#undef TFR
    return make_uint2(x0, x1);
}

// ---------------------------------------------------------------------------
// 512-pt complex FFT, f64, 256 threads
// ---------------------------------------------------------------------------
__device__ __forceinline__ void fft512d(double2* a, int tid, bool inverse) {
    #pragma unroll
    for (int rep = 0; rep < 2; rep++) {
        int i = tid + rep * 256;
        int j = __brev(i) >> 23;
        if (j > i) { double2 t = a[i]; a[i] = a[j]; a[j] = t; }
    }
    __syncthreads();
    #pragma unroll
    for (int s = 0; s < 9; s++) {
        int half = 1 << s;
        int pos  = tid & (half - 1);
        int i0   = ((tid >> s) << (s + 1)) + pos;
        int i1   = i0 + half;
        double2 t = g_twd1024[pos << (9 - s)];
        double ty = inverse ? -t.y : t.y;
        double2 u = a[i0], v = a[i1];
        double vr = v.x * t.x - v.y * ty;
        double vi = v.x * ty + v.y * t.x;
        a[i0] = make_double2(u.x + vr, u.y + vi);
        a[i1] = make_double2(u.x - vr, u.y - vi);
        __syncthreads();
    }
}

// ---------------------------------------------------------------------------
// 512-pt complex FFT, f32, 256 threads
// ---------------------------------------------------------------------------
__device__ __forceinline__ void fft512f(float2* a, int tid, bool inverse) {
    #pragma unroll
    for (int rep = 0; rep < 2; rep++) {
        int i = tid + rep * 256;
        int j = __brev(i) >> 23;
        if (j > i) { float2 t = a[i]; a[i] = a[j]; a[j] = t; }
    }
    __syncthreads();
    #pragma unroll
    for (int s = 0; s < 9; s++) {
        int half = 1 << s;
        int pos  = tid & (half - 1);
        int i0   = ((tid >> s) << (s + 1)) + pos;
        int i1   = i0 + half;
        float2 t = g_twdf1024[pos << (9 - s)];
        float ty = inverse ? -t.y : t.y;
        float2 u = a[i0], v = a[i1];
        float vr = v.x * t.x - v.y * ty;
        float vi = v.x * ty + v.y * t.x;
        a[i0] = make_float2(u.x + vr, u.y + vi);
        a[i1] = make_float2(u.x - vr, u.y - vi);
        __syncthreads();
    }
}

// ---------------------------------------------------------------------------
// Bilinear tap weights (compute_weight_mat f32 mimicry)
// ---------------------------------------------------------------------------
__device__ __forceinline__ void lin_weights(float p, int in_size,
                                            int& i0, int& i1,
                                            float& w0, float& w1) {
    int h0 = (int)floorf(p);
    int h1 = h0 + 1;
    float x0 = __fsub_rn(p, (float)h0);
    float x1 = __fsub_rn((float)h1, p);
    float a0 = (h0 >= 0 && h0 < in_size) ? __fsub_rn(1.0f, x0) : 0.0f;
    float a1 = (h1 >= 0 && h1 < in_size) ? __fsub_rn(1.0f, x1) : 0.0f;
    float tot = __fadd_rn(a0, a1);
    w0 = __fdiv_rn(a0, tot);
    w1 = __fdiv_rn(a1, tot);
    i0 = min(in_size - 1, max(0, h0));
    i1 = min(in_size - 1, max(0, h1));
}

__global__ void k_fullspec(const float* __restrict__ params, float* __restrict__ fs) {
    int i = blockIdx.x * blockDim.x + threadIdx.x;
    if (i >= OUT_FS) return;
    int w = i & 511;
    int h = (i >> 9) & 127;
    int b = i >> 16;
    float py = __fsub_rn(__fmul_rn(__fadd_rn((float)h, 0.5f), 0.25f),  0.5f);
    float px = __fsub_rn(__fmul_rn(__fadd_rn((float)w, 0.5f), 0.125f), 0.5f);
    int y0, y1, x0, x1; float wy0, wy1, wx0, wx1;
    lin_weights(py, GH, y0, y1, wy0, wy1);
    lin_weights(px, GW, x0, x1, wx0, wx1);
    const float* g = params + b * (GH*GW);
    float v00 = g[y0*GW + x0], v01 = g[y0*GW + x1];
    float v10 = g[y1*GW + x0], v11 = g[y1*GW + x1];
    float c0 = __fadd_rn(__fmul_rn(wy0, v00), __fmul_rn(wy1, v10));
    float c1 = __fadd_rn(__fmul_rn(wy0, v01), __fmul_rn(wy1, v11));
    fs[i] = __fadd_rn(__fmul_rn(wx0, c0), __fmul_rn(wx1, c1));
}

__global__ void k_mag(const float* __restrict__ fs) {
    int i = blockIdx.x * blockDim.x + threadIdx.x;
    if (i >= NTOT) return;
    int k  = i % NK;
    int bf = i / NK;
    int f  = bf & (NFRAMES - 1);
    int b  = bf >> 9;
    const float invs = (float)(128.0 / 513.0);
    float p = __fsub_rn(__fmul_rn(__fadd_rn((float)k, 0.5f), invs), 0.5f);
    int h0, h1; float w0, w1;
    lin_weights(p, FULL_H, h0, h1, w0, w1);
    const float* fb = fs + (size_t)b * (FULL_H * FULL_W);
    float a0 = fb[h0 * FULL_W + f];
    float a1 = fb[h1 * FULL_W + f];
    float sp0 = __fmul_rn(__fmul_rn(a0, a0), 100.0f);
    float sp1 = __fmul_rn(__fmul_rn(a1, a1), 100.0f);
    float v = __fadd_rn(__fmul_rn(w0, sp0), __fmul_rn(w1, sp1));
    g_mag[i] = sqrtf(fmaxf(v, 0.0f));
}

__global__ void k_init_phase() {
    int i = blockIdx.x * blockDim.x + threadIdx.x;
    if (i >= NTOT) return;
    int k  = i % NK;
    int bf = i / NK;
    int f  = bf & (NFRAMES - 1);
    int b  = bf >> 9;
    unsigned cnt = (unsigned)((b * NK + k) * NFRAMES + f);
    uint2 r = threefry_01(0u, cnt);
    unsigned bits = r.x ^ r.y;
    float u = __uint_as_float((bits >> 9) | 0x3f800000u) - 1.0f;
    float th = __fmul_rn(TWOPI_F, u);
    float cs = (float)cos((double)th);
    float sn = (float)sin((double)th);
    float m = g_mag[i];
    g_S[i] = make_float2(__fmul_rn(m, cs), __fmul_rn(m, sn));
    g_T[i] = make_float2(0.f, 0.f);
}

// ---------------------------------------------------------------------------
// ISTFT (f64): irfft via 512-pt complex IFFT (real packing), * win (f32)
// ---------------------------------------------------------------------------
__global__ void k_istft_frames() {
    int bf  = blockIdx.x;
    int tid = threadIdx.x;
    __shared__ double2 a[512];
    const float2* Sp = g_S + (size_t)bf * NK;
    #pragma unroll
    for (int rep = 0; rep < 2; rep++) {
        int k = tid + rep * 256;
        float2 xk = Sp[k];
        float2 xm = Sp[512 - k];
        double xky = (k == 0) ? 0.0 : (double)xk.y;
        double xmy = (k == 0) ? 0.0 : (double)xm.y;
        double Sx = (double)xk.x + (double)xm.x;
        double Sy = xky - xmy;
        double Dx = (double)xk.x - (double)xm.x;
        double Dy = xky + xmy;
        double2 t = g_twd1024[k];
        a[k] = make_double2(Sx - t.x * Dy + t.y * Dx,
                            Sy + t.x * Dx + t.y * Dy);
    }
    __syncthreads();
    fft512d(a, tid, true);
    float2* fr = (float2*)(g_frames + (size_t)bf * NFFT);
    #pragma unroll
    for (int rep = 0; rep < 2; rep++) {
        int m = tid + rep * 256;
        double2 ym = a[m];
        float y0 = (float)(ym.x * (1.0 / 1024.0));
        float y1 = (float)(ym.y * (1.0 / 1024.0));
        fr[m] = make_float2(__fmul_rn(y0, g_win[2*m]),
                            __fmul_rn(y1, g_win[2*m + 1]));
    }
}

// ---------------------------------------------------------------------------
// ISTFT (f32 variant)
// ---------------------------------------------------------------------------
__global__ void k_istft_frames_f32() {
    int bf  = blockIdx.x;
    int tid = threadIdx.x;
    __shared__ float2 a[512];
    const float2* Sp = g_S + (size_t)bf * NK;
    #pragma unroll
    for (int rep = 0; rep < 2; rep++) {
        int k = tid + rep * 256;
        float2 xk = Sp[k];
        float2 xm = Sp[512 - k];
        float xky = (k == 0) ? 0.0f : xk.y;
        float xmy = (k == 0) ? 0.0f : xm.y;
        float Sx = xk.x + xm.x;
        float Sy = xky - xmy;
        float Dx = xk.x - xm.x;
        float Dy = xky + xmy;
        float2 t = g_twdf1024[k];
        a[k] = make_float2(Sx - t.x * Dy + t.y * Dx,
                           Sy + t.x * Dx + t.y * Dy);
    }
    __syncthreads();
    fft512f(a, tid, true);
    float2* fr = (float2*)(g_frames + (size_t)bf * NFFT);
    #pragma unroll
    for (int rep = 0; rep < 2; rep++) {
        int m = tid + rep * 256;
        float2 ym = a[m];
        float y0 = ym.x * (1.0f / 1024.0f);
        float y1 = ym.y * (1.0f / 1024.0f);
        fr[m] = make_float2(__fmul_rn(y0, g_win[2*m]),
                            __fmul_rn(y1, g_win[2*m + 1]));
    }
}

// ---------------------------------------------------------------------------
// OLA
// ---------------------------------------------------------------------------
__global__ void k_ola() {
    int i = blockIdx.x * blockDim.x + threadIdx.x;
    if (i >= GB * LSIG) return;
    int b  = i / LSIG;
    int tp = i - b * LSIG;
    int t  = tp + 512;
    int fhi = min(NFRAMES - 1, t >> 8);
    int flo = max(0, (t - 768) >> 8);
    const float* fr = g_frames + (size_t)b * NFRAMES * NFFT;
    float s = 0.f, w2 = 0.f;
    for (int f = flo; f <= fhi; f++) {
        int n = t - (f << 8);
        s  = __fadd_rn(s,  fr[(size_t)f * NFFT + n]);
        w2 = __fadd_rn(w2, g_win2[n]);
    }
    float den = (w2 > 1e-11f) ? w2 : 1.0f;
    g_audio[i] = __fdiv_rn(s, den);
}

// ---------------------------------------------------------------------------
// STFT + GL update (f64 FFT)
// ---------------------------------------------------------------------------
__global__ void k_stft_update() {
    int bf  = blockIdx.x;
    int f   = bf & (NFRAMES - 1);
    int b   = bf >> 9;
    int tid = threadIdx.x;
    __shared__ double2 a[512];
    const float* au = g_audio + (size_t)b * LSIG;
    #pragma unroll
    for (int rep = 0; rep < 2; rep++) {
        int m = tid + rep * 256;
        int n0 = 2 * m, n1 = 2 * m + 1;
        int i0 = (f << 8) + n0 - 512;
        int i1 = i0 + 1;
        if (i0 < 0) i0 = -i0; else if (i0 >= LSIG) i0 = 2 * LSIG - 2 - i0;
        if (i1 < 0) i1 = -i1; else if (i1 >= LSIG) i1 = 2 * LSIG - 2 - i1;
        float xv0 = __fmul_rn(au[i0], g_win[n0]);
        float xv1 = __fmul_rn(au[i1], g_win[n1]);
        a[m] = make_double2((double)xv0, (double)xv1);
    }
    __syncthreads();
    fft512d(a, tid, false);
    size_t base = (size_t)bf * NK;
    const float cmom = (float)(0.99 / 1.99);
    for (int k = tid; k < NK; k += 256) {
        int m1 = (512 - k) & 511;
        double2 P = a[k & 511];
        double2 Q = a[m1];
        double Sx = P.x + Q.x, Sy = P.y - Q.y;
        double Dx = P.x - Q.x, Dy = P.y + Q.y;
        double2 t = g_twd1024[k];
        float Rx = (float)(0.5 * (Sx + t.x * Dy + t.y * Dx));
        float Ry = (float)(0.5 * (Sy - (t.x * Dx - t.y * Dy)));
        float2 tp = g_T[base + k];
        float ax = __fsub_rn(Rx, __fmul_rn(cmom, tp.x));
        float ay = __fsub_rn(Ry, __fmul_rn(cmom, tp.y));
        double dm = sqrt((double)ax * (double)ax + (double)ay * (double)ay);
        float d = __fadd_rn((float)dm, 1e-16f);
        float anx = __fdiv_rn(ax, d);
        float any = __fdiv_rn(ay, d);
        float m = g_mag[base + k];
        g_S[base + k] = make_float2(__fmul_rn(m, anx), __fmul_rn(m, any));
        g_T[base + k] = make_float2(Rx, Ry);
    }
}

// ---------------------------------------------------------------------------
// STFT + GL update (f32 FFT variant)
// ---------------------------------------------------------------------------
__global__ void k_stft_update_f32() {
    int bf  = blockIdx.x;
    int f   = bf & (NFRAMES - 1);
    int b   = bf >> 9;
    int tid = threadIdx.x;
    __shared__ float2 a[512];
    const float* au = g_audio + (size_t)b * LSIG;
    #pragma unroll
    for (int rep = 0; rep < 2; rep++) {
        int m = tid + rep * 256;
        int n0 = 2 * m, n1 = 2 * m + 1;
        int i0 = (f << 8) + n0 - 512;
        int i1 = i0 + 1;
        if (i0 < 0) i0 = -i0; else if (i0 >= LSIG) i0 = 2 * LSIG - 2 - i0;
        if (i1 < 0) i1 = -i1; else if (i1 >= LSIG) i1 = 2 * LSIG - 2 - i1;
        float xv0 = __fmul_rn(au[i0], g_win[n0]);
        float xv1 = __fmul_rn(au[i1], g_win[n1]);
        a[m] = make_float2(xv0, xv1);
    }
    __syncthreads();
    fft512f(a, tid, false);
    size_t base = (size_t)bf * NK;
    const float cmom = (float)(0.99 / 1.99);
    for (int k = tid; k < NK; k += 256) {
        int m1 = (512 - k) & 511;
        float2 P = a[k & 511];
        float2 Q = a[m1];
        float Sx = P.x + Q.x, Sy = P.y - Q.y;
        float Dx = P.x - Q.x, Dy = P.y + Q.y;
        float2 t = g_twdf1024[k];
        float Rx = 0.5f * (Sx + t.x * Dy + t.y * Dx);
        float Ry = 0.5f * (Sy - (t.x * Dx - t.y * Dy));
        float2 tp = g_T[base + k];
        float ax = __fsub_rn(Rx, __fmul_rn(cmom, tp.x));
        float ay = __fsub_rn(Ry, __fmul_rn(cmom, tp.y));
        double dm = sqrt((double)ax * (double)ax + (double)ay * (double)ay);
        float d = __fadd_rn((float)dm, 1e-16f);
        float anx = __fdiv_rn(ax, d);
        float any = __fdiv_rn(ay, d);
        float m = g_mag[base + k];
        g_S[base + k] = make_float2(__fmul_rn(m, anx), __fmul_rn(m, any));
        g_T[base + k] = make_float2(Rx, Ry);
    }
}

// ---------------------------------------------------------------------------
__global__ void k_max() {
    int b   = blockIdx.x;
    int tid = threadIdx.x;
    __shared__ float red[1024];
    const float* au = g_audio + (size_t)b * LSIG;
    float m = 0.f;
    for (int i = tid; i < LSIG; i += 1024) m = fmaxf(m, fabsf(au[i]));
    red[tid] = m;
    __syncthreads();
    for (int s = 512; s > 0; s >>= 1) {
        if (tid < s) red[tid] = fmaxf(red[tid], red[tid + s]);
        __syncthreads();
    }
    if (tid == 0) g_maxv[b] = fmaxf(red[0], 1e-8f);
}

__global__ void k_final(float* __restrict__ out) {
    int i = blockIdx.x * blockDim.x + threadIdx.x;
    if (i >= OUT_AUDIO) return;
    int b = i >> 17;
    int t = i & (NSAMP - 1);
    float v = 0.f;
    if (t < LSIG)
        v = __fmul_rn(__fdiv_rn(g_audio[(size_t)b * LSIG + t], g_maxv[b]), 0.9f);
    out[i] = v;
}

// ---------------------------------------------------------------------------
extern "C" void kernel_launch(void* const* d_in, const int* in_sizes, int n_in,
                              void* d_out, int out_size) {
    const float* params = (const float*)d_in[0];
    float* out = (float*)d_out;
    float* fs_out = out + OUT_AUDIO;

    k_init_tables<<<4, 256>>>();
    k_fullspec<<<(OUT_FS + 255) / 256, 256>>>(params, fs_out);
    k_mag<<<(NTOT + 255) / 256, 256>>>(fs_out);
    k_init_phase<<<(NTOT + 255) / 256, 256>>>();

    const int NBF = GB * NFRAMES;
    for (int it = 0; it < 32; it++) {
        if (it < N_F64_ITERS) {
            k_istft_frames<<<NBF, 256>>>();
            k_ola<<<(GB * LSIG + 255) / 256, 256>>>();
            k_stft_update<<<NBF, 256>>>();
        } else {
            k_istft_frames_f32<<<NBF, 256>>>();
            k_ola<<<(GB * LSIG + 255) / 256, 256>>>();
            k_stft_update_f32<<<NBF, 256>>>();
        }
    }
    k_istft_frames_f32<<<NBF, 256>>>();
    k_ola<<<(GB * LSIG + 255) / 256, 256>>>();
    k_max<<<GB, 1024>>>();
    k_final<<<(OUT_AUDIO + 255) / 256, 256>>>(out);
}

// round 7
// speedup vs baseline: 6.9548x; 1.4693x over previous
#include <cuda_runtime.h>
#include <math.h>
#include <stdint.h>

#define GB       8
#define GH       32
#define GW       64
#define FULL_H   128
#define FULL_W   512
#define NFFT     1024
#define HOP      256
#define NK       513
#define NFRAMES  512
#define LSIG     130816
#define NSAMP    131072
#define NTOT     (GB*NFRAMES*NK)
#define OUT_AUDIO (GB*NSAMP)
#define OUT_FS    (GB*FULL_H*FULL_W)

#define TWOPI_F  6.28318548202514648438f   /* f32(2*pi) */

// ---------------------------------------------------------------------------
// Device scratch
// ---------------------------------------------------------------------------
__device__ float   g_win[NFFT];
__device__ float   g_win2[NFFT];
__device__ float2  g_twdf1024[NK];    // e^{-2pi i k/1024}, f32 (rounded from f64)
__device__ float   g_mag[NTOT];
__device__ float2  g_S[NTOT];         // only used for initial spectrum
__device__ float2  g_T[NTOT];
__device__ float   g_frames[GB*NFRAMES*NFFT];
__device__ float   g_audio[GB*LSIG];
__device__ float   g_maxv[GB];

// ---------------------------------------------------------------------------
__global__ void k_init_tables() {
    int i = blockIdx.x * blockDim.x + threadIdx.x;
    if (i < NFFT) {
        float af = __fdiv_rn(__fmul_rn(TWOPI_F, (float)i), 1024.0f);
        float c  = (float)cos((double)af);
        float w  = __fmul_rn(0.5f, __fsub_rn(1.0f, c));
        g_win[i]  = w;
        g_win2[i] = __fmul_rn(w, w);
    }
    if (i < NK) {
        double a = 2.0 * M_PI * (double)i / 1024.0;
        g_twdf1024[i] = make_float2((float)cos(a), (float)(-sin(a)));
    }
}

// ---------------------------------------------------------------------------
// threefry2x32, key (0,1)
// ---------------------------------------------------------------------------
__device__ __forceinline__ unsigned rotl32(unsigned x, int r) {
    return (x << r) | (x >> (32 - r));
}
__device__ __forceinline__ uint2 threefry_01(unsigned c0, unsigned c1) {
    const unsigned k0 = 0u, k1 = 1u;
    const unsigned k2 = 0x1BD11BDAu ^ k0 ^ k1;
    unsigned x0 = c0 + k0, x1 = c1 + k1;
#define TFR(r) { x0 += x1; x1 = rotl32(x1, (r)); x1 ^= x0; }
    TFR(13) TFR(15) TFR(26) TFR(6)
    x0 += k1; x1 += k2 + 1u;
    TFR(17) TFR(29) TFR(16) TFR(24)
    x0 += k2; x1 += k0 + 2u;
    TFR(13) TFR(15) TFR(26) TFR(6)
    x0 += k0; x1 += k1 + 3u;
    TFR(17) TFR(29) TFR(16) TFR(24)
    x0 += k1; x1 += k2 + 4u;
    TFR(13) TFR(15) TFR(26) TFR(6)
    x0 += k2; x1 += k0 + 5u;
#undef TFR
    return make_uint2(x0, x1);
}

// ---------------------------------------------------------------------------
// 512-pt complex FFT, f32, 256 threads. Caller syncs before entry.
// ---------------------------------------------------------------------------
__device__ __forceinline__ void fft512f(float2* a, int tid, bool inverse) {
    #pragma unroll
    for (int rep = 0; rep < 2; rep++) {
        int i = tid + rep * 256;
        int j = __brev(i) >> 23;
        if (j > i) { float2 t = a[i]; a[i] = a[j]; a[j] = t; }
    }
    __syncthreads();
    #pragma unroll
    for (int s = 0; s < 9; s++) {
        int half = 1 << s;
        int pos  = tid & (half - 1);
        int i0   = ((tid >> s) << (s + 1)) + pos;
        int i1   = i0 + half;
        float2 t = g_twdf1024[pos << (9 - s)];
        float ty = inverse ? -t.y : t.y;
        float2 u = a[i0], v = a[i1];
        float vr = v.x * t.x - v.y * ty;
        float vi = v.x * ty + v.y * t.x;
        a[i0] = make_float2(u.x + vr, u.y + vi);
        a[i1] = make_float2(u.x - vr, u.y - vi);
        __syncthreads();
    }
}

// ---------------------------------------------------------------------------
// Bilinear tap weights (compute_weight_mat f32 mimicry)
// ---------------------------------------------------------------------------
__device__ __forceinline__ void lin_weights(float p, int in_size,
                                            int& i0, int& i1,
                                            float& w0, float& w1) {
    int h0 = (int)floorf(p);
    int h1 = h0 + 1;
    float x0 = __fsub_rn(p, (float)h0);
    float x1 = __fsub_rn((float)h1, p);
    float a0 = (h0 >= 0 && h0 < in_size) ? __fsub_rn(1.0f, x0) : 0.0f;
    float a1 = (h1 >= 0 && h1 < in_size) ? __fsub_rn(1.0f, x1) : 0.0f;
    float tot = __fadd_rn(a0, a1);
    w0 = __fdiv_rn(a0, tot);
    w1 = __fdiv_rn(a1, tot);
    i0 = min(in_size - 1, max(0, h0));
    i1 = min(in_size - 1, max(0, h1));
}

__global__ void k_fullspec(const float* __restrict__ params, float* __restrict__ fs) {
    int i = blockIdx.x * blockDim.x + threadIdx.x;
    if (i >= OUT_FS) return;
    int w = i & 511;
    int h = (i >> 9) & 127;
    int b = i >> 16;
    float py = __fsub_rn(__fmul_rn(__fadd_rn((float)h, 0.5f), 0.25f),  0.5f);
    float px = __fsub_rn(__fmul_rn(__fadd_rn((float)w, 0.5f), 0.125f), 0.5f);
    int y0, y1, x0, x1; float wy0, wy1, wx0, wx1;
    lin_weights(py, GH, y0, y1, wy0, wy1);
    lin_weights(px, GW, x0, x1, wx0, wx1);
    const float* g = params + b * (GH*GW);
    float v00 = g[y0*GW + x0], v01 = g[y0*GW + x1];
    float v10 = g[y1*GW + x0], v11 = g[y1*GW + x1];
    float c0 = __fadd_rn(__fmul_rn(wy0, v00), __fmul_rn(wy1, v10));
    float c1 = __fadd_rn(__fmul_rn(wy0, v01), __fmul_rn(wy1, v11));
    fs[i] = __fadd_rn(__fmul_rn(wx0, c0), __fmul_rn(wx1, c1));
}

__global__ void k_mag(const float* __restrict__ fs) {
    int i = blockIdx.x * blockDim.x + threadIdx.x;
    if (i >= NTOT) return;
    int k  = i % NK;
    int bf = i / NK;
    int f  = bf & (NFRAMES - 1);
    int b  = bf >> 9;
    const float invs = (float)(128.0 / 513.0);
    float p = __fsub_rn(__fmul_rn(__fadd_rn((float)k, 0.5f), invs), 0.5f);
    int h0, h1; float w0, w1;
    lin_weights(p, FULL_H, h0, h1, w0, w1);
    const float* fb = fs + (size_t)b * (FULL_H * FULL_W);
    float a0 = fb[h0 * FULL_W + f];
    float a1 = fb[h1 * FULL_W + f];
    float sp0 = __fmul_rn(__fmul_rn(a0, a0), 100.0f);
    float sp1 = __fmul_rn(__fmul_rn(a1, a1), 100.0f);
    float v = __fadd_rn(__fmul_rn(w0, sp0), __fmul_rn(w1, sp1));
    g_mag[i] = sqrtf(fmaxf(v, 0.0f));
}

__global__ void k_init_phase() {
    int i = blockIdx.x * blockDim.x + threadIdx.x;
    if (i >= NTOT) return;
    int k  = i % NK;
    int bf = i / NK;
    int f  = bf & (NFRAMES - 1);
    int b  = bf >> 9;
    unsigned cnt = (unsigned)((b * NK + k) * NFRAMES + f);
    uint2 r = threefry_01(0u, cnt);
    unsigned bits = r.x ^ r.y;
    float u = __uint_as_float((bits >> 9) | 0x3f800000u) - 1.0f;
    float th = __fmul_rn(TWOPI_F, u);
    float sn, cs;
    sincosf(th, &sn, &cs);
    float m = g_mag[i];
    g_S[i] = make_float2(__fmul_rn(m, cs), __fmul_rn(m, sn));
    g_T[i] = make_float2(0.f, 0.f);
}

// ---------------------------------------------------------------------------
// ISTFT (f32): irfft via 512-pt complex IFFT (real packing), * win.
// Used once, for the initial spectrum.
// ---------------------------------------------------------------------------
__global__ void k_istft_frames_f32() {
    int bf  = blockIdx.x;
    int tid = threadIdx.x;
    __shared__ float2 a[512];
    const float2* Sp = g_S + (size_t)bf * NK;
    #pragma unroll
    for (int rep = 0; rep < 2; rep++) {
        int k = tid + rep * 256;
        float2 xk = Sp[k];
        float2 xm = Sp[512 - k];
        float xky = (k == 0) ? 0.0f : xk.y;
        float xmy = (k == 0) ? 0.0f : xm.y;
        float Sx = xk.x + xm.x;
        float Sy = xky - xmy;
        float Dx = xk.x - xm.x;
        float Dy = xky + xmy;
        float2 t = g_twdf1024[k];
        a[k] = make_float2(Sx - t.x * Dy + t.y * Dx,
                           Sy + t.x * Dx + t.y * Dy);
    }
    __syncthreads();
    fft512f(a, tid, true);
    float2* fr = (float2*)(g_frames + (size_t)bf * NFFT);
    #pragma unroll
    for (int rep = 0; rep < 2; rep++) {
        int m = tid + rep * 256;
        float2 ym = a[m];
        float y0 = ym.x * (1.0f / 1024.0f);
        float y1 = ym.y * (1.0f / 1024.0f);
        fr[m] = make_float2(__fmul_rn(y0, g_win[2*m]),
                            __fmul_rn(y1, g_win[2*m + 1]));
    }
}

// ---------------------------------------------------------------------------
// OLA
// ---------------------------------------------------------------------------
__global__ void k_ola() {
    int i = blockIdx.x * blockDim.x + threadIdx.x;
    if (i >= GB * LSIG) return;
    int b  = i / LSIG;
    int tp = i - b * LSIG;
    int t  = tp + 512;
    int fhi = min(NFRAMES - 1, t >> 8);
    int flo = max(0, (t - 768) >> 8);
    const float* fr = g_frames + (size_t)b * NFRAMES * NFFT;
    float s = 0.f, w2 = 0.f;
    for (int f = flo; f <= fhi; f++) {
        int n = t - (f << 8);
        s  = __fadd_rn(s,  fr[(size_t)f * NFFT + n]);
        w2 = __fadd_rn(w2, g_win2[n]);
    }
    float den = (w2 > 1e-11f) ? w2 : 1.0f;
    g_audio[i] = __fdiv_rn(s, den);
}

// ---------------------------------------------------------------------------
// FUSED: forward STFT + GL momentum update + inverse ISTFT of the new S row.
// S row never touches global memory.
// ---------------------------------------------------------------------------
__global__ void k_fused_update_istft() {
    int bf  = blockIdx.x;
    int f   = bf & (NFRAMES - 1);
    int b   = bf >> 9;
    int tid = threadIdx.x;
    __shared__ float2 a[512];
    __shared__ float2 Srow[NK];

    // --- load windowed audio frame (reflect pad) ---
    const float* au = g_audio + (size_t)b * LSIG;
    #pragma unroll
    for (int rep = 0; rep < 2; rep++) {
        int m = tid + rep * 256;
        int n0 = 2 * m, n1 = 2 * m + 1;
        int i0 = (f << 8) + n0 - 512;
        int i1 = i0 + 1;
        if (i0 < 0) i0 = -i0; else if (i0 >= LSIG) i0 = 2 * LSIG - 2 - i0;
        if (i1 < 0) i1 = -i1; else if (i1 >= LSIG) i1 = 2 * LSIG - 2 - i1;
        float xv0 = __fmul_rn(au[i0], g_win[n0]);
        float xv1 = __fmul_rn(au[i1], g_win[n1]);
        a[m] = make_float2(xv0, xv1);
    }
    __syncthreads();

    // --- forward FFT (real packing) ---
    fft512f(a, tid, false);

    // --- unpack + GL update; new S row into smem ---
    size_t base = (size_t)bf * NK;
    const float cmom = (float)(0.99 / 1.99);
    for (int k = tid; k < NK; k += 256) {
        int m1 = (512 - k) & 511;
        float2 P = a[k & 511];
        float2 Q = a[m1];
        float Sx = P.x + Q.x, Sy = P.y - Q.y;
        float Dx = P.x - Q.x, Dy = P.y + Q.y;
        float2 t = g_twdf1024[k];
        float Rx = 0.5f * (Sx + t.x * Dy + t.y * Dx);
        float Ry = 0.5f * (Sy - (t.x * Dx - t.y * Dy));
        float2 tp = g_T[base + k];
        float ax = __fsub_rn(Rx, __fmul_rn(cmom, tp.x));
        float ay = __fsub_rn(Ry, __fmul_rn(cmom, tp.y));
        double dm = sqrt((double)ax * (double)ax + (double)ay * (double)ay);
        float d = __fadd_rn((float)dm, 1e-16f);
        float anx = __fdiv_rn(ax, d);
        float any = __fdiv_rn(ay, d);
        float m = g_mag[base + k];
        Srow[k] = make_float2(__fmul_rn(m, anx), __fmul_rn(m, any));
        g_T[base + k] = make_float2(Rx, Ry);
    }
    __syncthreads();

    // --- repack hermitian row for inverse FFT ---
    #pragma unroll
    for (int rep = 0; rep < 2; rep++) {
        int k = tid + rep * 256;
        float2 xk = Srow[k];
        float2 xm = Srow[512 - k];
        float xky = (k == 0) ? 0.0f : xk.y;
        float xmy = (k == 0) ? 0.0f : xm.y;
        float Sx = xk.x + xm.x;
        float Sy = xky - xmy;
        float Dx = xk.x - xm.x;
        float Dy = xky + xmy;
        float2 t = g_twdf1024[k];
        a[k] = make_float2(Sx - t.x * Dy + t.y * Dx,
                           Sy + t.x * Dx + t.y * Dy);
    }
    __syncthreads();

    // --- inverse FFT + window + write frames ---
    fft512f(a, tid, true);
    float2* fr = (float2*)(g_frames + (size_t)bf * NFFT);
    #pragma unroll
    for (int rep = 0; rep < 2; rep++) {
        int m = tid + rep * 256;
        float2 ym = a[m];
        float y0 = ym.x * (1.0f / 1024.0f);
        float y1 = ym.y * (1.0f / 1024.0f);
        fr[m] = make_float2(__fmul_rn(y0, g_win[2*m]),
                            __fmul_rn(y1, g_win[2*m + 1]));
    }
}

// ---------------------------------------------------------------------------
__global__ void k_max() {
    int b   = blockIdx.x;
    int tid = threadIdx.x;
    __shared__ float red[1024];
    const float* au = g_audio + (size_t)b * LSIG;
    float m = 0.f;
    for (int i = tid; i < LSIG; i += 1024) m = fmaxf(m, fabsf(au[i]));
    red[tid] = m;
    __syncthreads();
    for (int s = 512; s > 0; s >>= 1) {
        if (tid < s) red[tid] = fmaxf(red[tid], red[tid + s]);
        __syncthreads();
    }
    if (tid == 0) g_maxv[b] = fmaxf(red[0], 1e-8f);
}

__global__ void k_final(float* __restrict__ out) {
    int i = blockIdx.x * blockDim.x + threadIdx.x;
    if (i >= OUT_AUDIO) return;
    int b = i >> 17;
    int t = i & (NSAMP - 1);
    float v = 0.f;
    if (t < LSIG)
        v = __fmul_rn(__fdiv_rn(g_audio[(size_t)b * LSIG + t], g_maxv[b]), 0.9f);
    out[i] = v;
}

// ---------------------------------------------------------------------------
extern "C" void kernel_launch(void* const* d_in, const int* in_sizes, int n_in,
                              void* d_out, int out_size) {
    const float* params = (const float*)d_in[0];
    float* out = (float*)d_out;
    float* fs_out = out + OUT_AUDIO;

    k_init_tables<<<4, 256>>>();
    k_fullspec<<<(OUT_FS + 255) / 256, 256>>>(params, fs_out);
    k_mag<<<(NTOT + 255) / 256, 256>>>(fs_out);
    k_init_phase<<<(NTOT + 255) / 256, 256>>>();

    const int NBF = GB * NFRAMES;
    // initial ISTFT from S0
    k_istft_frames_f32<<<NBF, 256>>>();
    // 32 GL iterations: OLA then fused (STFT + update + ISTFT of new S)
    for (int it = 0; it < 32; it++) {
        k_ola<<<(GB * LSIG + 255) / 256, 256>>>();
        k_fused_update_istft<<<NBF, 256>>>();
    }
    // final OLA over the frames produced by the last fused kernel
    k_ola<<<(GB * LSIG + 255) / 256, 256>>>();
    k_max<<<GB, 1024>>>();
    k_final<<<(OUT_AUDIO + 255) / 256, 256>>>(out);
}